// round 12
// baseline (speedup 1.0000x reference)
#include <cuda_runtime.h>
#include <cuda_fp16.h>
#include <cstdint>
#include <math.h>

#define DIM 257
#define SEQ 2048
#define NB  8
#define BT  (NB * SEQ)        // 16384
#define KP  320               // padded K storage (5 chunks of 64)
#define NPA 384               // padded N for B-operand buffers
#define KC  64                // k halves per pipeline chunk (128B rows)
#define ASTR 72               // smem row stride in halves (144B; ldmatrix conflict-free)
#define TILE_B (128 * ASTR * 2)            // bytes per smem tile (18432)
#define SMEM_BYTES (2 * 2 * TILE_B)        // 73728

// ---------------- static device scratch (fp16 storage, fp32 accumulate) ----------------
__device__ __align__(16) __half g_x[3][(size_t)BT * KP];     // padded q,k,v
__device__ __align__(16) __half g_W[4][(size_t)NPA * KP];    // padded weights (K-major)
__device__ float g_b[4][NPA];                                // padded biases (fp32)
__device__ __align__(16) __half g_qp[(size_t)BT * KP];       // projected Q
__device__ __align__(16) __half g_kp[(size_t)BT * KP];       // projected K
__device__ __align__(16) __half g_vt[(size_t)NB * NPA * SEQ];// V projected, transposed [b][n][t]
__device__ __align__(16) __half g_s[(size_t)NB * SEQ * SEQ]; // sigmoid scores
__device__ __align__(16) __half g_ct[(size_t)BT * KP];       // context

// ---------------- helpers ----------------
__device__ __forceinline__ uint32_t s2u(const void* p) {
    uint32_t a;
    asm("{ .reg .u64 t; cvta.to.shared.u64 t, %1; cvt.u32.u64 %0, t; }" : "=r"(a) : "l"(p));
    return a;
}
__device__ __forceinline__ void cp16(uint32_t dst, const void* src) {
    asm volatile("cp.async.cg.shared.global [%0], [%1], 16;" :: "r"(dst), "l"(src));
}
#define LDMX4(r0, r1, r2, r3, addr) \
    asm volatile("ldmatrix.sync.aligned.m8n8.x4.shared.b16 {%0,%1,%2,%3}, [%4];" \
        : "=r"(r0), "=r"(r1), "=r"(r2), "=r"(r3) : "r"(addr))

__device__ __forceinline__ void mma_f16(float* d, const uint32_t* a, const uint32_t* b) {
    asm volatile(
        "mma.sync.aligned.m16n8k16.row.col.f32.f16.f16.f32 "
        "{%0,%1,%2,%3}, {%4,%5,%6,%7}, {%8,%9}, {%0,%1,%2,%3};"
        : "+f"(d[0]), "+f"(d[1]), "+f"(d[2]), "+f"(d[3])
        : "r"(a[0]), "r"(a[1]), "r"(a[2]), "r"(a[3]), "r"(b[0]), "r"(b[1]));
}

// ---------------- prep kernels (pad + fp16 round) ----------------
__global__ void prep_x(const float* __restrict__ q, const float* __restrict__ k,
                       const float* __restrict__ v) {
    int i = blockIdx.x * 256 + threadIdx.x;
    if (i >= BT * KP) return;
    int r = i / KP, c = i - r * KP;
    long long si = (long long)r * DIM + c;
    g_x[0][i] = (c < DIM) ? __float2half_rn(q[si]) : __float2half_rn(0.f);
    g_x[1][i] = (c < DIM) ? __float2half_rn(k[si]) : __float2half_rn(0.f);
    g_x[2][i] = (c < DIM) ? __float2half_rn(v[si]) : __float2half_rn(0.f);
}
__global__ void prep_w(const float* W0, const float* b0, const float* W1, const float* b1,
                       const float* W2, const float* b2, const float* W3, const float* b3) {
    int i = blockIdx.x * 256 + threadIdx.x;
    const float* Ws[4] = {W0, W1, W2, W3};
    const float* bs[4] = {b0, b1, b2, b3};
    const int per = NPA * KP;
    if (i < 4 * per) {
        int w = i / per, rem = i - w * per, r = rem / KP, c = rem - r * KP;
        g_W[w][(size_t)r * KP + c] =
            (r < DIM && c < DIM) ? __float2half_rn(Ws[w][r * DIM + c]) : __float2half_rn(0.f);
    }
    if (i < 4 * NPA) {
        int w = i / NPA, n = i - w * NPA;
        g_b[w][n] = (n < DIM) ? bs[w][n] : 0.f;
    }
}

// ---------------- fp16 tensor-core GEMM: D[m,n] = sum_k A[m,k]*B[n,k] ----------------
// 128x128 CTA tile, 8 warps (256 thr), 32x64 warp tile (4x2 warp grid).
// ldmatrix fragments, m16n8k16 MMA.
// MASKN: runtime nf-mask (nmma) skips padded-N MMAs (compile-time removable).
// ks_last: number of k16 steps executed in the FINAL chunk (1..4) — trims K padding.
// MODE 0: (+bias if non-null) -> fp16 -> C[m*ldc+n], n < nstore
// MODE 2: sigmoid(v*scale) -> fp16 -> C[m*ldc+n]
// MODE 3: +bias -> fp32 exact -> Cf[m*ldc+n], n < nstore  (final out)
// MODE 4: fused QKV: bz selects input/weight/bias from globals; bz<2 -> qp/kp
//         normal store (nstore=KP); bz==2 -> transposed V^T store (nstore=NPA)
template <int MODE, bool MASKN>
__global__ __launch_bounds__(256, 2)
void gemm(const __half* __restrict__ A, long long sA, int lda,
          const __half* __restrict__ B, long long sB, int ldb,
          int kc, int ks_last, __half* __restrict__ C, float* __restrict__ Cf,
          long long sC, int ldc,
          int nstore, int nmma, const float* __restrict__ bias, float scale)
{
    extern __shared__ __align__(16) char sm[];
    const int tid = threadIdx.x, wid = tid >> 5, lane = tid & 31;
    const int g = lane >> 2, t = lane & 3;
    const int lrow = lane & 7, seg = lane >> 3;
    const int bz = blockIdx.z, m0 = blockIdx.y * 128, n0 = blockIdx.x * 128;
    const int wm = (wid >> 1) * 32, wn = (wid & 1) * 64;

    if (MODE == 4) {
        A = g_x[bz]; B = g_W[bz]; bias = g_b[bz];
        nstore = (bz == 2) ? NPA : KP;
    }

    // warp-uniform count of live 8-wide n-fragments in this warp's 64-col slab
    int nfmax = 8;
    if (MASKN) {
        const int nrem = nmma - n0 - wn;
        nfmax = (nrem >= 64) ? 8 : ((nrem > 0) ? ((nrem + 7) >> 3) : 0);
    }

    const __half* Ab = A + (MODE == 4 ? 0 : bz * sA) + (long long)m0 * lda;
    const __half* Bb = B + (MODE == 4 ? 0 : bz * sB) + (long long)n0 * ldb;
    const uint32_t sb = s2u(sm);

    auto load = [&](int ck, int buf) {
        const char* ag = (const char*)(Ab + ck * KC);
        const char* bg = (const char*)(Bb + ck * KC);
        uint32_t da = sb + (uint32_t)buf * (2 * TILE_B);
        uint32_t db = da + TILE_B;
        #pragma unroll
        for (int i = 0; i < 4; i++) {
            int e = tid + i * 256;               // 0..1023
            int r = e >> 3, c = e & 7;
            uint32_t off = (uint32_t)(r * (ASTR * 2) + c * 16);
            cp16(da + off, ag + (long long)r * lda * 2 + c * 16);
            cp16(db + off, bg + (long long)r * ldb * 2 + c * 16);
        }
        asm volatile("cp.async.commit_group;" ::: "memory");
    };

    // per-thread ldmatrix base offsets (bytes within a tile)
    const uint32_t aoff = (uint32_t)((wm + lrow + (seg & 1) * 8) * (ASTR * 2) + (seg >> 1) * 16);
    const uint32_t boff = (uint32_t)((wn + lrow + (seg >> 1) * 8) * (ASTR * 2) + (seg & 1) * 16);

    float acc[2][8][4] = {};
    load(0, 0);

    for (int ck = 0; ck < kc; ++ck) {
        const int buf = ck & 1;
        if (ck + 1 < kc) {
            load(ck + 1, buf ^ 1);
            asm volatile("cp.async.wait_group 1;" ::: "memory");
        } else {
            asm volatile("cp.async.wait_group 0;" ::: "memory");
        }
        __syncthreads();

        const uint32_t ta = sb + (uint32_t)buf * (2 * TILE_B);
        const uint32_t tb = ta + TILE_B;
        const int ksn = (ck == kc - 1) ? ks_last : 4;

        #pragma unroll
        for (int ks = 0; ks < 4; ks++) {        // up to four k16 steps per 64-half chunk
            if (ks >= ksn) break;
            const uint32_t kbyte = (uint32_t)(ks * 32);
            uint32_t fa[2][4], fb[8][2];
            #pragma unroll
            for (int mf = 0; mf < 2; mf++) {
                LDMX4(fa[mf][0], fa[mf][1], fa[mf][2], fa[mf][3],
                      ta + aoff + (uint32_t)mf * (16 * ASTR * 2) + kbyte);
            }
            #pragma unroll
            for (int j = 0; j < 4; j++) {
                if (!MASKN || 2 * j < nfmax) {
                    uint32_t r0, r1, r2, r3;
                    LDMX4(r0, r1, r2, r3,
                          tb + boff + (uint32_t)j * (16 * ASTR * 2) + kbyte);
                    fb[2 * j][0] = r0; fb[2 * j][1] = r1;
                    fb[2 * j + 1][0] = r2; fb[2 * j + 1][1] = r3;
                }
            }
            #pragma unroll
            for (int mf = 0; mf < 2; mf++)
                #pragma unroll
                for (int nf = 0; nf < 8; nf++)
                    if (!MASKN || nf < nfmax)
                        mma_f16(acc[mf][nf], fa[mf], fb[nf]);
        }
        __syncthreads();
    }

    // ---- epilogue ----
    const bool vtrans = (MODE == 4) && (bz == 2);
    const int bi = m0 / SEQ;
    const int tl0 = m0 % SEQ;

    #pragma unroll
    for (int mf = 0; mf < 2; mf++) {
        #pragma unroll
        for (int half = 0; half < 2; half++) {
            const int mloc = wm + mf * 16 + g + half * 8;
            const int m = m0 + mloc;
            #pragma unroll
            for (int nf = 0; nf < 8; nf++) {
                const int n = n0 + wn + nf * 8 + 2 * t;
                if (n >= nstore) continue;
                float v0 = acc[mf][nf][half * 2 + 0];
                float v1 = acc[mf][nf][half * 2 + 1];
                if (MODE == 2) {
                    v0 = 1.0f / (1.0f + __expf(-v0 * scale));
                    v1 = 1.0f / (1.0f + __expf(-v1 * scale));
                } else {
                    if (bias) { v0 += bias[n]; v1 += bias[n + 1 < NPA ? n + 1 : n]; }
                }
                if (MODE == 4) {
                    if (vtrans) {
                        const int tl = tl0 + mloc;
                        __half* dst = g_vt + ((long long)(bi * NPA + n)) * SEQ + tl;
                        dst[0] = __float2half_rn(v0);
                        if (n + 1 < nstore) dst[SEQ] = __float2half_rn(v1);
                    } else {
                        __half* dst = (bz ? g_kp : g_qp) + (long long)m * KP + n;
                        __half2 h2;
                        h2.x = __float2half_rn(v0);
                        h2.y = __float2half_rn(v1);
                        *(__half2*)dst = h2;
                    }
                } else if (MODE == 3) {
                    float* dst = Cf + bz * sC + (long long)m * ldc + n;
                    dst[0] = v0;
                    if (n + 1 < nstore) dst[1] = v1;
                } else {
                    __half* dst = C + bz * sC + (long long)m * ldc + n;
                    __half2 h2;
                    h2.x = __float2half_rn(v0);
                    h2.y = __float2half_rn(v1);
                    *(__half2*)dst = h2;                 // n even, ldc even
                }
            }
        }
    }
}

// ---------------- host ----------------
extern "C" void kernel_launch(void* const* d_in, const int* in_sizes, int n_in,
                              void* d_out, int out_size)
{
    const float* q  = (const float*)d_in[0];
    const float* k  = (const float*)d_in[1];
    const float* v  = (const float*)d_in[2];
    const float* Wq = (const float*)d_in[3];
    const float* bq = (const float*)d_in[4];
    const float* Wk = (const float*)d_in[5];
    const float* bk = (const float*)d_in[6];
    const float* Wv = (const float*)d_in[7];
    const float* bv = (const float*)d_in[8];
    const float* Wo = (const float*)d_in[9];
    const float* bo = (const float*)d_in[10];
    float* out = (float*)d_out;

    __half *W, *qp, *kp, *vt, *s, *ct;
    float* bb;
    cudaGetSymbolAddress((void**)&W,  g_W);
    cudaGetSymbolAddress((void**)&bb, g_b);
    cudaGetSymbolAddress((void**)&qp, g_qp);
    cudaGetSymbolAddress((void**)&kp, g_kp);
    cudaGetSymbolAddress((void**)&vt, g_vt);
    cudaGetSymbolAddress((void**)&s,  g_s);
    cudaGetSymbolAddress((void**)&ct, g_ct);

    cudaFuncSetAttribute((const void*)gemm<0, true>,  cudaFuncAttributeMaxDynamicSharedMemorySize, SMEM_BYTES);
    cudaFuncSetAttribute((const void*)gemm<2, false>, cudaFuncAttributeMaxDynamicSharedMemorySize, SMEM_BYTES);
    cudaFuncSetAttribute((const void*)gemm<3, true>,  cudaFuncAttributeMaxDynamicSharedMemorySize, SMEM_BYTES);
    cudaFuncSetAttribute((const void*)gemm<4, true>,  cudaFuncAttributeMaxDynamicSharedMemorySize, SMEM_BYTES);

    const float scale = 1.0f / sqrtf((float)DIM);
    const size_t ws = (size_t)NPA * KP;

    prep_x<<<(BT * KP + 255) / 256, 256>>>(q, k, v);
    prep_w<<<(4 * NPA * KP + 255) / 256, 256>>>(Wq, bq, Wk, bk, Wv, bv, Wo, bo);

    // 1) fused QKV projections: grid.z selects input (0=q,1=k,2=v->V^T); K=257 -> 17 k16 steps
    dim3 gf(3, BT / 128, 3);
    gemm<4, true><<<gf, 256, SMEM_BYTES>>>(nullptr, 0, KP, nullptr, 0, KP, KP / KC, 1,
                                           nullptr, nullptr, 0, KP, 0, DIM, nullptr, 0.f);

    // 2) scores = sigmoid(qp @ kp^T * scale), per batch [2048,2048]; full N, K=257
    dim3 gs(SEQ / 128, SEQ / 128, NB);
    gemm<2, false><<<gs, 256, SMEM_BYTES>>>(qp, (long long)SEQ * KP, KP,
                                            kp, (long long)SEQ * KP, KP, KP / KC, 1,
                                            s, nullptr, (long long)SEQ * SEQ, SEQ, SEQ, SEQ,
                                            nullptr, scale);

    // 3) ctx = scores @ V   (B = V^T [384, 2048] per batch, K = 2048, full chunks)
    dim3 gc(3, SEQ / 128, NB);
    gemm<0, true><<<gc, 256, SMEM_BYTES>>>(s, (long long)SEQ * SEQ, SEQ,
                                           vt, (long long)NPA * SEQ, SEQ, SEQ / KC, 4,
                                           ct, nullptr, (long long)SEQ * KP, KP, KP, DIM,
                                           nullptr, 0.f);

    // 4) out = ctx @ Wo^T + bo  (fp32 exact store, [BT, 257]); K=257
    dim3 gp(3, BT / 128, 1);
    gemm<3, true><<<gp, 256, SMEM_BYTES>>>(ct, 0, KP, W + 3 * ws, 0, KP, KP / KC, 1,
                                           nullptr, out, 0, DIM, DIM, DIM, bb + 3 * NPA, 0.f);
}

// round 13
// speedup vs baseline: 1.0347x; 1.0347x over previous
#include <cuda_runtime.h>
#include <cuda_fp16.h>
#include <cstdint>
#include <math.h>

#define DIM 257
#define SEQ 2048
#define NB  8
#define BT  (NB * SEQ)        // 16384
#define KP  320               // padded K storage (5 chunks of 64)
#define NPA 384               // padded N for B-operand buffers
#define KC  64                // k halves per pipeline chunk (128B rows)
#define ASTR 72               // smem row stride in halves (144B; ldmatrix conflict-free)

// ---------------- static device scratch (fp16 storage, fp32 accumulate) ----------------
__device__ __align__(16) __half g_x[3][(size_t)BT * KP];     // padded q,k,v
__device__ __align__(16) __half g_W[4][(size_t)NPA * KP];    // padded weights (K-major); slot2 = W' = Wo@Wv
__device__ float g_b[4][NPA];                                // padded biases; slot2 = b' = Wo@bv
__device__ __align__(16) __half g_qp[(size_t)BT * KP];       // projected Q
__device__ __align__(16) __half g_kp[(size_t)BT * KP];       // projected K
__device__ __align__(16) __half g_vt[(size_t)NB * NPA * SEQ];// u = v@W'^T + b', transposed [b][n][t]
__device__ __align__(16) __half g_s[(size_t)NB * SEQ * SEQ]; // sigmoid scores

// ---------------- helpers ----------------
__device__ __forceinline__ uint32_t s2u(const void* p) {
    uint32_t a;
    asm("{ .reg .u64 t; cvta.to.shared.u64 t, %1; cvt.u32.u64 %0, t; }" : "=r"(a) : "l"(p));
    return a;
}
__device__ __forceinline__ void cp16(uint32_t dst, const void* src) {
    asm volatile("cp.async.cg.shared.global [%0], [%1], 16;" :: "r"(dst), "l"(src));
}
__device__ __forceinline__ float tanh_ap(float x) {
    float r;
    asm("tanh.approx.f32 %0, %1;" : "=f"(r) : "f"(x));
    return r;
}
#define LDMX4(r0, r1, r2, r3, addr) \
    asm volatile("ldmatrix.sync.aligned.m8n8.x4.shared.b16 {%0,%1,%2,%3}, [%4];" \
        : "=r"(r0), "=r"(r1), "=r"(r2), "=r"(r3) : "r"(addr))

__device__ __forceinline__ void mma_f16(float* d, const uint32_t* a, const uint32_t* b) {
    asm volatile(
        "mma.sync.aligned.m16n8k16.row.col.f32.f16.f16.f32 "
        "{%0,%1,%2,%3}, {%4,%5,%6,%7}, {%8,%9}, {%0,%1,%2,%3};"
        : "+f"(d[0]), "+f"(d[1]), "+f"(d[2]), "+f"(d[3])
        : "r"(a[0]), "r"(a[1]), "r"(a[2]), "r"(a[3]), "r"(b[0]), "r"(b[1]));
}

// ---------------- prep kernels ----------------
__global__ void prep_x(const float* __restrict__ q, const float* __restrict__ k,
                       const float* __restrict__ v) {
    int i = blockIdx.x * 256 + threadIdx.x;
    if (i >= BT * KP) return;
    int r = i / KP, c = i - r * KP;
    long long si = (long long)r * DIM + c;
    g_x[0][i] = (c < DIM) ? __float2half_rn(q[si]) : __float2half_rn(0.f);
    g_x[1][i] = (c < DIM) ? __float2half_rn(k[si]) : __float2half_rn(0.f);
    g_x[2][i] = (c < DIM) ? __float2half_rn(v[si]) : __float2half_rn(0.f);
}
__global__ void prep_w(const float* W0, const float* b0, const float* W1, const float* b1,
                       const float* W2, const float* b2, const float* W3, const float* b3) {
    int i = blockIdx.x * 256 + threadIdx.x;
    const float* Ws[4] = {W0, W1, W2, W3};
    const float* bs[4] = {b0, b1, b2, b3};
    const int per = NPA * KP;
    if (i < 4 * per) {
        int w = i / per, rem = i - w * per, r = rem / KP, c = rem - r * KP;
        g_W[w][(size_t)r * KP + c] =
            (r < DIM && c < DIM) ? __float2half_rn(Ws[w][r * DIM + c]) : __float2half_rn(0.f);
    }
    if (i < 4 * NPA) {
        int w = i / NPA, n = i - w * NPA;
        g_b[w][n] = (n < DIM) ? bs[w][n] : 0.f;
    }
}
// W' = Wo @ Wv (fp32 accumulate -> fp16, K-major into g_W[2]); b' = Wo @ bv -> g_b[2].
// 4 output rows per block; Wv column reads coalesced and L2-resident.
#define WPR 4
__global__ void prep_wp(const float* __restrict__ Wo, const float* __restrict__ Wv,
                        const float* __restrict__ bv) {
    __shared__ float wo[WPR][DIM];
    const int nb = blockIdx.x * WPR;
    const int tid = threadIdx.x;
    for (int e = tid; e < WPR * DIM; e += 256) {
        int r = e / DIM, c = e - r * DIM;
        wo[r][c] = (nb + r < DIM) ? Wo[(nb + r) * DIM + c] : 0.f;
    }
    __syncthreads();
    for (int k0 = tid; k0 < KP; k0 += 256) {
        float acc[WPR] = {};
        if (k0 < DIM) {
            for (int j = 0; j < DIM; j++) {
                float wv = Wv[j * DIM + k0];
                #pragma unroll
                for (int r = 0; r < WPR; r++) acc[r] += wo[r][j] * wv;
            }
        }
        #pragma unroll
        for (int r = 0; r < WPR; r++) {
            int n = nb + r;
            if (n < DIM) g_W[2][(size_t)n * KP + k0] = __float2half_rn(acc[r]);
        }
    }
    if (tid < WPR) {
        int n = nb + tid;
        if (n < DIM) {
            float a = 0.f;
            for (int j = 0; j < DIM; j++) a += wo[tid][j] * bv[j];
            g_b[2][n] = a;
        }
    }
}

// ---------------- fp16 tensor-core GEMM: D[m,n] = sum_k A[m,k]*B[n,k] ----------------
// MTILE x 128 CTA tile, 8 warps (256 thr). MTILE=128: warp grid 4x2 (warp tile 32x64);
// MTILE=64: warp grid 2x4 (warp tile 32x32). ldmatrix fragments, m16n8k16 MMA.
// MASKN: runtime nf-mask (nmma) skips padded-N MMAs. ks_last trims K padding in final chunk.
// MODE 2: sigmoid via tanh: 0.5*tanh(v*scale2)+0.5 -> fp16 -> C
// MODE 3: +bias -> fp32 exact -> Cf (final out)
// MODE 4: fused QKV: bz selects input/weight/bias from globals; bz<2 -> qp/kp;
//         bz==2 -> u projection with transposed store to g_vt
template <int MODE, bool MASKN, int MTILE>
__global__ __launch_bounds__(256, 2)
void gemm(const __half* __restrict__ A, long long sA, int lda,
          const __half* __restrict__ B, long long sB, int ldb,
          int kc, int ks_last, __half* __restrict__ C, float* __restrict__ Cf,
          long long sC, int ldc,
          int nstore, int nmma, const float* __restrict__ bias, float scale2)
{
    constexpr int NWN = (MTILE == 128) ? 2 : 4;   // warps along n
    constexpr int WNW = (MTILE == 128) ? 64 : 32; // warp n width
    constexpr int NF  = WNW / 8;                  // n fragments per warp
    constexpr int ATILE_B = MTILE * ASTR * 2;
    constexpr int BTILE_B = 128 * ASTR * 2;
    constexpr int STAGE_B = ATILE_B + BTILE_B;

    extern __shared__ __align__(16) char sm[];
    const int tid = threadIdx.x, wid = tid >> 5, lane = tid & 31;
    const int g = lane >> 2, t = lane & 3;
    const int lrow = lane & 7, seg = lane >> 3;
    const int bz = blockIdx.z, m0 = blockIdx.y * MTILE, n0 = blockIdx.x * 128;
    const int wm = (wid / NWN) * 32, wn = (wid % NWN) * WNW;

    const __half* Ap = A;
    const __half* Bp = B;
    if (MODE == 4) {
        Ap = g_x[bz]; Bp = g_W[bz]; bias = g_b[bz];
        nstore = (bz == 2) ? NPA : KP;
    }

    int nfmax = NF;
    if (MASKN) {
        const int nrem = nmma - n0 - wn;
        nfmax = (nrem >= WNW) ? NF : ((nrem > 0) ? ((nrem + 7) >> 3) : 0);
    }

    const __half* Ab = Ap + (MODE == 4 ? 0 : bz * sA) + (long long)m0 * lda;
    const __half* Bb = Bp + (MODE == 4 ? 0 : bz * sB) + (long long)n0 * ldb;
    const uint32_t sb = s2u(sm);

    auto load = [&](int ck, int buf) {
        const char* ag = (const char*)(Ab + ck * KC);
        const char* bg = (const char*)(Bb + ck * KC);
        uint32_t da = sb + (uint32_t)buf * STAGE_B;
        uint32_t db = da + ATILE_B;
        #pragma unroll
        for (int i = 0; i < MTILE * 8 / 256; i++) {
            int e = tid + i * 256;
            int r = e >> 3, c = e & 7;
            uint32_t off = (uint32_t)(r * (ASTR * 2) + c * 16);
            cp16(da + off, ag + (long long)r * lda * 2 + c * 16);
        }
        #pragma unroll
        for (int i = 0; i < 4; i++) {
            int e = tid + i * 256;
            int r = e >> 3, c = e & 7;
            uint32_t off = (uint32_t)(r * (ASTR * 2) + c * 16);
            cp16(db + off, bg + (long long)r * ldb * 2 + c * 16);
        }
        asm volatile("cp.async.commit_group;" ::: "memory");
    };

    const uint32_t aoff = (uint32_t)((wm + lrow + (seg & 1) * 8) * (ASTR * 2) + (seg >> 1) * 16);
    const uint32_t boff = (uint32_t)((wn + lrow + (seg >> 1) * 8) * (ASTR * 2) + (seg & 1) * 16);

    float acc[2][NF][4] = {};
    load(0, 0);

    for (int ck = 0; ck < kc; ++ck) {
        const int buf = ck & 1;
        if (ck + 1 < kc) {
            load(ck + 1, buf ^ 1);
            asm volatile("cp.async.wait_group 1;" ::: "memory");
        } else {
            asm volatile("cp.async.wait_group 0;" ::: "memory");
        }
        __syncthreads();

        const uint32_t ta = sb + (uint32_t)buf * STAGE_B;
        const uint32_t tb = ta + ATILE_B;
        const int ksn = (ck == kc - 1) ? ks_last : 4;

        #pragma unroll
        for (int ks = 0; ks < 4; ks++) {
            if (ks >= ksn) break;
            const uint32_t kbyte = (uint32_t)(ks * 32);
            uint32_t fa[2][4], fb[NF][2];
            #pragma unroll
            for (int mf = 0; mf < 2; mf++) {
                LDMX4(fa[mf][0], fa[mf][1], fa[mf][2], fa[mf][3],
                      ta + aoff + (uint32_t)mf * (16 * ASTR * 2) + kbyte);
            }
            #pragma unroll
            for (int j = 0; j < NF / 2; j++) {
                if (!MASKN || 2 * j < nfmax) {
                    uint32_t r0, r1, r2, r3;
                    LDMX4(r0, r1, r2, r3,
                          tb + boff + (uint32_t)j * (16 * ASTR * 2) + kbyte);
                    fb[2 * j][0] = r0; fb[2 * j][1] = r1;
                    fb[2 * j + 1][0] = r2; fb[2 * j + 1][1] = r3;
                }
            }
            #pragma unroll
            for (int mf = 0; mf < 2; mf++)
                #pragma unroll
                for (int nf = 0; nf < NF; nf++)
                    if (!MASKN || nf < nfmax)
                        mma_f16(acc[mf][nf], fa[mf], fb[nf]);
        }
        __syncthreads();
    }

    // ---- epilogue ----
    const bool vtrans = (MODE == 4) && (bz == 2);
    const int bi = m0 / SEQ;
    const int tl0 = m0 % SEQ;

    #pragma unroll
    for (int mf = 0; mf < 2; mf++) {
        #pragma unroll
        for (int half = 0; half < 2; half++) {
            const int mloc = wm + mf * 16 + g + half * 8;
            const int m = m0 + mloc;
            #pragma unroll
            for (int nf = 0; nf < NF; nf++) {
                const int n = n0 + wn + nf * 8 + 2 * t;
                if (n >= nstore) continue;
                float v0 = acc[mf][nf][half * 2 + 0];
                float v1 = acc[mf][nf][half * 2 + 1];
                if (MODE == 2) {
                    v0 = fmaf(tanh_ap(v0 * scale2), 0.5f, 0.5f);
                    v1 = fmaf(tanh_ap(v1 * scale2), 0.5f, 0.5f);
                } else {
                    if (bias) { v0 += bias[n]; v1 += bias[n + 1 < NPA ? n + 1 : n]; }
                }
                if (MODE == 4) {
                    if (vtrans) {
                        const int tl = tl0 + mloc;
                        __half* dst = g_vt + ((long long)(bi * NPA + n)) * SEQ + tl;
                        dst[0] = __float2half_rn(v0);
                        if (n + 1 < nstore) dst[SEQ] = __float2half_rn(v1);
                    } else {
                        __half* dst = (bz ? g_kp : g_qp) + (long long)m * KP + n;
                        __half2 h2;
                        h2.x = __float2half_rn(v0);
                        h2.y = __float2half_rn(v1);
                        *(__half2*)dst = h2;
                    }
                } else if (MODE == 3) {
                    float* dst = Cf + bz * sC + (long long)m * ldc + n;
                    dst[0] = v0;
                    if (n + 1 < nstore) dst[1] = v1;
                } else {
                    __half* dst = C + bz * sC + (long long)m * ldc + n;
                    __half2 h2;
                    h2.x = __float2half_rn(v0);
                    h2.y = __float2half_rn(v1);
                    *(__half2*)dst = h2;                 // n even, ldc even
                }
            }
        }
    }
}

// ---------------- host ----------------
extern "C" void kernel_launch(void* const* d_in, const int* in_sizes, int n_in,
                              void* d_out, int out_size)
{
    const float* q  = (const float*)d_in[0];
    const float* k  = (const float*)d_in[1];
    const float* v  = (const float*)d_in[2];
    const float* Wq = (const float*)d_in[3];
    const float* bq = (const float*)d_in[4];
    const float* Wk = (const float*)d_in[5];
    const float* bk = (const float*)d_in[6];
    const float* Wv = (const float*)d_in[7];
    const float* bv = (const float*)d_in[8];
    const float* Wo = (const float*)d_in[9];
    const float* bo = (const float*)d_in[10];
    float* out = (float*)d_out;

    __half *qp, *kp, *vt, *s;
    float* bb;
    cudaGetSymbolAddress((void**)&bb, g_b);
    cudaGetSymbolAddress((void**)&qp, g_qp);
    cudaGetSymbolAddress((void**)&kp, g_kp);
    cudaGetSymbolAddress((void**)&vt, g_vt);
    cudaGetSymbolAddress((void**)&s,  g_s);

    constexpr int SMEM128 = 2 * ((128 + 128) * ASTR * 2);   // 73728
    constexpr int SMEM64  = 2 * ((64 + 128) * ASTR * 2);    // 55296
    cudaFuncSetAttribute((const void*)gemm<2, false, 128>, cudaFuncAttributeMaxDynamicSharedMemorySize, SMEM128);
    cudaFuncSetAttribute((const void*)gemm<4, true, 128>,  cudaFuncAttributeMaxDynamicSharedMemorySize, SMEM128);
    cudaFuncSetAttribute((const void*)gemm<3, true, 64>,   cudaFuncAttributeMaxDynamicSharedMemorySize, SMEM64);

    const float scale2 = 0.5f / sqrtf((float)DIM);

    prep_x<<<(BT * KP + 255) / 256, 256>>>(q, k, v);
    prep_w<<<(4 * NPA * KP + 255) / 256, 256>>>(Wq, bq, Wk, bk, Wv, bv, Wo, bo);
    prep_wp<<<(DIM + WPR - 1) / WPR, 256>>>(Wo, Wv, bv);

    // 1) fused QKV projections: grid.z selects input (0=q,1=k,2=v->u^T via W',b')
    dim3 gf(3, BT / 128, 3);
    gemm<4, true, 128><<<gf, 256, SMEM128>>>(nullptr, 0, KP, nullptr, 0, KP, KP / KC, 1,
                                             nullptr, nullptr, 0, KP, 0, DIM, nullptr, 0.f);

    // 2) scores = sigmoid(qp @ kp^T * scale) via tanh, per batch [2048,2048]
    dim3 gs(SEQ / 128, SEQ / 128, NB);
    gemm<2, false, 128><<<gs, 256, SMEM128>>>(qp, (long long)SEQ * KP, KP,
                                              kp, (long long)SEQ * KP, KP, KP / KC, 1,
                                              s, nullptr, (long long)SEQ * SEQ, SEQ, SEQ, SEQ,
                                              nullptr, scale2);

    // 3) out = S @ u + bo  (B = u^T [384, 2048] per batch, K = 2048; fp32 store)
    dim3 go(3, SEQ / 64, NB);
    gemm<3, true, 64><<<go, 256, SMEM64>>>(s, (long long)SEQ * SEQ, SEQ,
                                           vt, (long long)NPA * SEQ, SEQ, SEQ / KC, 4,
                                           nullptr, out, (long long)SEQ * DIM, DIM, DIM, DIM,
                                           bb + 3 * NPA, 0.f);
}